// round 13
// baseline (speedup 1.0000x reference)
#include <cuda_runtime.h>
#include <cuda_fp16.h>
#include <math.h>

#define N_NODES 16384
#define N_EDGES 262144
#define HEADS   4
#define HID     128
#define HF      (HEADS * HID)   // 512
#define SLOPE   0.2f

// ---------------- scratch (device globals) ----------------------------------
__device__ __half g_fs1h[N_NODES * HF];   // fp16 gather copy (layer1 src feats)
__device__ float g_fd1[N_NODES * HF];
__device__ float g_out1[N_NODES * HF];
__device__ __half g_fs2h[N_NODES * HID];  // fp16 gather copy (layer2 src feats)
__device__ float g_fd2[N_NODES * HID];
__device__ float g_out2[N_NODES * HID];
__device__ int   g_cnt[N_NODES];
__device__ int   g_rowptr[N_NODES + 1];
__device__ int   g_cur[N_NODES];
__device__ int   g_csrc[N_EDGES];

// ---------------- CSR build --------------------------------------------------
__global__ void hist_k(const int* __restrict__ dst) {
    int i = blockIdx.x * blockDim.x + threadIdx.x;
    if (i < N_EDGES) atomicAdd(&g_cnt[dst[i]], 1);
}

__global__ void scan_k() {
    __shared__ int sh[1024];
    int t = threadIdx.x;
    int base = t * 16;
    int loc[16];
    int s = 0;
#pragma unroll
    for (int i = 0; i < 16; i++) { loc[i] = s; s += g_cnt[base + i]; }
    sh[t] = s;
    __syncthreads();
    for (int off = 1; off < 1024; off <<= 1) {
        int v = 0;
        if (t >= off) v = sh[t - off];
        __syncthreads();
        sh[t] += v;
        __syncthreads();
    }
    int pre = (t == 0) ? 0 : sh[t - 1];
#pragma unroll
    for (int i = 0; i < 16; i++) {
        int rp = pre + loc[i];
        g_rowptr[base + i] = rp;
        g_cur[base + i]    = rp;
    }
    if (t == 1023) g_rowptr[N_NODES] = sh[1023];
}

__global__ void scatter_k(const int* __restrict__ src, const int* __restrict__ dst) {
    int i = blockIdx.x * blockDim.x + threadIdx.x;
    if (i < N_EDGES) {
        int p = atomicAdd(&g_cur[dst[i]], 1);
        g_csrc[p] = src[i];
    }
}

// ---------------- helpers ----------------------------------------------------
__device__ __forceinline__ unsigned f2tf(float f) {
    unsigned u;
    asm("cvt.rna.tf32.f32 %0, %1;" : "=r"(u) : "f"(f));
    return u;
}

__device__ __forceinline__ void cpa16(void* s, const void* g) {
    unsigned sa = (unsigned)__cvta_generic_to_shared(s);
    asm volatile("cp.async.cg.shared.global [%0], [%1], 16;" :: "r"(sa), "l"(g));
}
#define CP_COMMIT() asm volatile("cp.async.commit_group;")
#define CP_WAIT(n)  asm volatile("cp.async.wait_group %0;" :: "n"(n))

// ---------------- tf32 GEMM (round-3 config) ---------------------------------
// blockIdx.z==0: C written as fp16 into Ch (src-projected feats, gather copy).
// blockIdx.z==1: C written as fp32 into Cf (dst-projected feats).
__global__ __launch_bounds__(256)
void tf32gemm_k(const float* __restrict__ A, int lda,
                const float* __restrict__ B0, const float* __restrict__ B1,
                const float* __restrict__ bias0, const float* __restrict__ bias1,
                __half* __restrict__ Ch, float* __restrict__ Cf,
                int ldb, int ldc, int K) {
    const float* B    = blockIdx.z ? B1 : B0;
    const float* bias = blockIdx.z ? bias1 : bias0;

    __shared__ float As[2][128][20];
    __shared__ float Bs[2][16][136];

    const int t = threadIdx.x;
    const int lane = t & 31, wid = t >> 5;
    const int warp_m = wid >> 2, warp_n = wid & 3;
    const int bm = blockIdx.x * 128, bn = blockIdx.y * 128;

    const int arow = t >> 1;
    const int ac   = (t & 1) * 8;
    const int brow = t >> 5;
    const int bc   = lane * 4;

    const float* Ag  = A + (size_t)(bm + arow) * lda + ac;
    const float* Bg0 = B + (size_t)brow * ldb + bn + bc;
    const float* Bg1 = B + (size_t)(brow + 8) * ldb + bn + bc;

    const int r_lo = lane >> 2;
    const int k_lo = lane & 3;
    const int nch = K >> 4;

    float acc[4][4][4];
#pragma unroll
    for (int i = 0; i < 4; i++)
#pragma unroll
        for (int j = 0; j < 4; j++)
#pragma unroll
            for (int k = 0; k < 4; k++) acc[i][j][k] = 0.f;

    auto issue = [&](int buf, int kc) {
        const float* ag = Ag + kc * 16;
        cpa16(&As[buf][arow][ac],     ag);
        cpa16(&As[buf][arow][ac + 4], ag + 4);
        cpa16(&Bs[buf][brow][bc],     Bg0 + (size_t)kc * 16 * ldb);
        cpa16(&Bs[buf][brow + 8][bc], Bg1 + (size_t)kc * 16 * ldb);
    };

    issue(0, 0);
    CP_COMMIT();

    for (int kc = 0; kc < nch; kc++) {
        if (kc + 1 < nch) {
            issue((kc + 1) & 1, kc + 1);
            CP_COMMIT();
            CP_WAIT(1);
        } else {
            CP_WAIT(0);
        }
        __syncthreads();

        const int buf = kc & 1;
#pragma unroll
        for (int ks = 0; ks < 16; ks += 8) {
            unsigned af[4][4], bf[4][2];
#pragma unroll
            for (int mf = 0; mf < 4; mf++) {
                int r0 = warp_m * 64 + mf * 16 + r_lo;
                int k0 = ks + k_lo;
                af[mf][0] = f2tf(As[buf][r0][k0]);
                af[mf][1] = f2tf(As[buf][r0 + 8][k0]);
                af[mf][2] = f2tf(As[buf][r0][k0 + 4]);
                af[mf][3] = f2tf(As[buf][r0 + 8][k0 + 4]);
            }
#pragma unroll
            for (int nf = 0; nf < 4; nf++) {
                int n0 = warp_n * 32 + nf * 8 + r_lo;
                int k0 = ks + k_lo;
                bf[nf][0] = f2tf(Bs[buf][k0][n0]);
                bf[nf][1] = f2tf(Bs[buf][k0 + 4][n0]);
            }
#pragma unroll
            for (int mf = 0; mf < 4; mf++)
#pragma unroll
                for (int nf = 0; nf < 4; nf++) {
                    asm("mma.sync.aligned.m16n8k8.row.col.f32.tf32.tf32.f32 "
                        "{%0,%1,%2,%3}, {%4,%5,%6,%7}, {%8,%9}, {%0,%1,%2,%3};"
                        : "+f"(acc[mf][nf][0]), "+f"(acc[mf][nf][1]),
                          "+f"(acc[mf][nf][2]), "+f"(acc[mf][nf][3])
                        : "r"(af[mf][0]), "r"(af[mf][1]), "r"(af[mf][2]), "r"(af[mf][3]),
                          "r"(bf[nf][0]), "r"(bf[nf][1]));
                }
        }
        __syncthreads();
    }

#pragma unroll
    for (int mf = 0; mf < 4; mf++) {
        int r = bm + warp_m * 64 + mf * 16 + r_lo;
#pragma unroll
        for (int nf = 0; nf < 4; nf++) {
            int c = bn + warp_n * 32 + nf * 8 + 2 * k_lo;
            float bb0 = bias[c], bb1 = bias[c + 1];
            float v00 = acc[mf][nf][0] + bb0, v01 = acc[mf][nf][1] + bb1;
            float v10 = acc[mf][nf][2] + bb0, v11 = acc[mf][nf][3] + bb1;
            if (blockIdx.z == 0) {
                __half2 h0 = { __float2half_rn(v00), __float2half_rn(v01) };
                __half2 h1 = { __float2half_rn(v10), __float2half_rn(v11) };
                *(__half2*)&Ch[(size_t)r * ldc + c] = h0;
                *(__half2*)&Ch[(size_t)(r + 8) * ldc + c] = h1;
            } else {
                float2 v0 = { v00, v01 };
                float2 v1 = { v10, v11 };
                *(float2*)&Cf[(size_t)r * ldc + c] = v0;
                *(float2*)&Cf[(size_t)(r + 8) * ldc + c] = v1;
            }
        }
    }
}

// ---------------- fp32 SGEMM (head, split-K atomics) -------------------------
__global__ __launch_bounds__(256)
void sgemm_atomic_k(const float* __restrict__ A, int lda,
                    const float* __restrict__ B, int ldb,
                    float* __restrict__ C, int ldc,
                    int Kchunk) {
    __shared__ float As[16][68];
    __shared__ float Bs[16][64];
    int tid = threadIdx.x;
    int bm = blockIdx.x * 64, bn = blockIdx.y * 64;
    int kstart = blockIdx.z * Kchunk;
    int tx = tid & 15, ty = tid >> 4;

    int arow = tid >> 2;
    int akk  = (tid & 3) * 4;
    int brow = tid >> 4;
    int bcol = (tid & 15) * 4;

    const float* Ap = A + (size_t)(bm + arow) * lda + kstart + akk;
    const float* Bp = B + (size_t)(kstart + brow) * ldb + bn + bcol;

    float acc[4][4] = {};
    for (int k = 0; k < Kchunk; k += 16) {
        float4 a = *(const float4*)Ap; Ap += 16;
        float4 b = *(const float4*)Bp; Bp += (size_t)16 * ldb;
        As[akk + 0][arow] = a.x;
        As[akk + 1][arow] = a.y;
        As[akk + 2][arow] = a.z;
        As[akk + 3][arow] = a.w;
        *(float4*)&Bs[brow][bcol] = b;
        __syncthreads();
#pragma unroll
        for (int kk = 0; kk < 16; kk++) {
            float a0 = As[kk][ty * 4 + 0];
            float a1 = As[kk][ty * 4 + 1];
            float a2 = As[kk][ty * 4 + 2];
            float a3 = As[kk][ty * 4 + 3];
            float4 bq = *(const float4*)&Bs[kk][tx * 4];
            acc[0][0] += a0 * bq.x; acc[0][1] += a0 * bq.y; acc[0][2] += a0 * bq.z; acc[0][3] += a0 * bq.w;
            acc[1][0] += a1 * bq.x; acc[1][1] += a1 * bq.y; acc[1][2] += a1 * bq.z; acc[1][3] += a1 * bq.w;
            acc[2][0] += a2 * bq.x; acc[2][1] += a2 * bq.y; acc[2][2] += a2 * bq.z; acc[2][3] += a2 * bq.w;
            acc[3][0] += a3 * bq.x; acc[3][1] += a3 * bq.y; acc[3][2] += a3 * bq.z; acc[3][3] += a3 * bq.w;
        }
        __syncthreads();
    }
#pragma unroll
    for (int i = 0; i < 4; i++) {
        int row = bm + ty * 4 + i;
#pragma unroll
        for (int j = 0; j < 4; j++) {
            int col = bn + tx * 4 + j;
            atomicAdd(&C[(size_t)row * ldc + col], acc[i][j]);
        }
    }
}

// ---------------- GAT shared pieces ------------------------------------------
__device__ __forceinline__ float4 ldhf4(const __half* p) {
    uint2 u = *(const uint2*)p;
    __half2 h0 = *(__half2*)&u.x;
    __half2 h1 = *(__half2*)&u.y;
    float2 f0 = __half22float2(h0);
    float2 f1 = __half22float2(h1);
    float4 f;
    f.x = f0.x; f.y = f0.y; f.z = f1.x; f.w = f1.y;
    return f;
}

__device__ __forceinline__ float edge_dot(float4 fs, float4 fdv, float4 av) {
    float e0 = fs.x + fdv.x; e0 = e0 > 0.f ? e0 : SLOPE * e0;
    float e1 = fs.y + fdv.y; e1 = e1 > 0.f ? e1 : SLOPE * e1;
    float e2 = fs.z + fdv.z; e2 = e2 > 0.f ? e2 : SLOPE * e2;
    float e3 = fs.w + fdv.w; e3 = e3 > 0.f ? e3 : SLOPE * e3;
    return e0 * av.x + e1 * av.y + e2 * av.z + e3 * av.w;
}

__device__ __forceinline__ float wreduce(float d) {
#pragma unroll
    for (int o = 16; o; o >>= 1) d += __shfl_xor_sync(0xffffffffu, d, o);
    return d;
}

__device__ __forceinline__ void online_upd(float& m, float& ssum, float4& acc,
                                           float d, float4 fs) {
    float mn = fmaxf(m, d);
    float sc = __expf(m - mn);
    float p  = __expf(d - mn);
    ssum = ssum * sc + p;
    acc.x = acc.x * sc + p * fs.x;
    acc.y = acc.y * sc + p * fs.y;
    acc.z = acc.z * sc + p * fs.z;
    acc.w = acc.w * sc + p * fs.w;
    m = mn;
}

// ---------------- GAT layer 1: 4 warps (1 per head), 4x batching, fp16 gather
__global__ __launch_bounds__(128)
void gat1_k(const float* __restrict__ attn1) {
    int n = blockIdx.x;
    int h = threadIdx.x >> 5;
    int lane = threadIdx.x & 31;
    __shared__ float s_fd[HF];
    __shared__ float s_at[HF];
    for (int i = threadIdx.x; i < HF; i += 128) {
        s_fd[i] = g_fd1[(size_t)n * HF + i];
        s_at[i] = attn1[i];
    }
    __syncthreads();

    int beg = g_rowptr[n], end = g_rowptr[n + 1];
    float4 fdv = *(const float4*)&s_fd[h * HID + lane * 4];
    float4 av  = *(const float4*)&s_at[h * HID + lane * 4];

    float m = -1e30f, ssum = 0.f;
    float4 acc = {0.f, 0.f, 0.f, 0.f};

    int e = beg;
    for (; e + 4 <= end; e += 4) {
        int s0 = g_csrc[e], s1 = g_csrc[e + 1], s2 = g_csrc[e + 2], s3 = g_csrc[e + 3];
        float4 f0 = ldhf4(&g_fs1h[(size_t)s0 * HF + h * HID + lane * 4]);
        float4 f1 = ldhf4(&g_fs1h[(size_t)s1 * HF + h * HID + lane * 4]);
        float4 f2 = ldhf4(&g_fs1h[(size_t)s2 * HF + h * HID + lane * 4]);
        float4 f3 = ldhf4(&g_fs1h[(size_t)s3 * HF + h * HID + lane * 4]);
        float d0 = wreduce(edge_dot(f0, fdv, av));
        float d1 = wreduce(edge_dot(f1, fdv, av));
        float d2 = wreduce(edge_dot(f2, fdv, av));
        float d3 = wreduce(edge_dot(f3, fdv, av));
        online_upd(m, ssum, acc, d0, f0);
        online_upd(m, ssum, acc, d1, f1);
        online_upd(m, ssum, acc, d2, f2);
        online_upd(m, ssum, acc, d3, f3);
    }
    for (; e < end; ++e) {
        int s = g_csrc[e];
        float4 fs = ldhf4(&g_fs1h[(size_t)s * HF + h * HID + lane * 4]);
        float d = wreduce(edge_dot(fs, fdv, av));
        online_upd(m, ssum, acc, d, fs);
    }

    float inv = (end > beg) ? 1.f / ssum : 0.f;
    float4 v;
    v.x = acc.x * inv; v.x = v.x > 0.f ? v.x : expm1f(v.x);
    v.y = acc.y * inv; v.y = v.y > 0.f ? v.y : expm1f(v.y);
    v.z = acc.z * inv; v.z = v.z > 0.f ? v.z : expm1f(v.z);
    v.w = acc.w * inv; v.w = v.w > 0.f ? v.w : expm1f(v.w);
    *(float4*)&g_out1[(size_t)n * HF + h * HID + lane * 4] = v;
}

// ---------------- GAT layer 2: 4 warps, 2x batching, fp16 gather -------------
__global__ __launch_bounds__(128)
void gat2_k(const float* __restrict__ attn2) {
    int n = blockIdx.x;
    int t = threadIdx.x;
    int warp = t >> 5, lane = t & 31;
    __shared__ float s_fd[HID];
    __shared__ float s_at[HID];
    __shared__ float s_m[4], s_s[4];
    __shared__ float s_acc[4][HID];
    if (t < HID) { s_fd[t] = g_fd2[(size_t)n * HID + t]; s_at[t] = attn2[t]; }
    __syncthreads();

    float4 fdv = *(const float4*)&s_fd[lane * 4];
    float4 av  = *(const float4*)&s_at[lane * 4];
    int beg = g_rowptr[n], end = g_rowptr[n + 1];

    float m = -1e30f, ssum = 0.f;
    float4 acc = {0.f, 0.f, 0.f, 0.f};
    int e = beg + warp;
    for (; e + 4 < end; e += 8) {
        int s0 = g_csrc[e], s1 = g_csrc[e + 4];
        float4 f0 = ldhf4(&g_fs2h[(size_t)s0 * HID + lane * 4]);
        float4 f1 = ldhf4(&g_fs2h[(size_t)s1 * HID + lane * 4]);
        float d0 = wreduce(edge_dot(f0, fdv, av));
        float d1 = wreduce(edge_dot(f1, fdv, av));
        online_upd(m, ssum, acc, d0, f0);
        online_upd(m, ssum, acc, d1, f1);
    }
    for (; e < end; e += 4) {
        int s = g_csrc[e];
        float4 fs = ldhf4(&g_fs2h[(size_t)s * HID + lane * 4]);
        float d = wreduce(edge_dot(fs, fdv, av));
        online_upd(m, ssum, acc, d, fs);
    }
    if (lane == 0) { s_m[warp] = m; s_s[warp] = ssum; }
    *(float4*)&s_acc[warp][lane * 4] = acc;
    __syncthreads();

    if (t < HID) {
        float M = fmaxf(fmaxf(s_m[0], s_m[1]), fmaxf(s_m[2], s_m[3]));
        float S = s_s[0] * __expf(s_m[0] - M) + s_s[1] * __expf(s_m[1] - M) +
                  s_s[2] * __expf(s_m[2] - M) + s_s[3] * __expf(s_m[3] - M);
        float v = 0.f;
        if (S > 0.f) {
            v = s_acc[0][t] * __expf(s_m[0] - M) + s_acc[1][t] * __expf(s_m[1] - M) +
                s_acc[2][t] * __expf(s_m[2] - M) + s_acc[3][t] * __expf(s_m[3] - M);
            v /= S;
        }
        v = v > 0.f ? v : expm1f(v);
        g_out2[(size_t)n * HID + t] = v;
    }
}

__global__ void initout_k(float* __restrict__ out, const float* __restrict__ bn) {
    int i = blockIdx.x * blockDim.x + threadIdx.x;
    if (i < 256 * 128) out[i] = bn[i & 127];
}

// ---------------- launch -----------------------------------------------------
static void* sym(const void* s) { void* p = nullptr; cudaGetSymbolAddress(&p, s); return p; }

extern "C" void kernel_launch(void* const* d_in, const int* in_sizes, int n_in,
                              void* d_out, int out_size) {
    const float* feat  = (const float*)d_in[0];
    const int*   src   = (const int*)d_in[1];
    const int*   dst   = (const int*)d_in[2];
    const float* W1s   = (const float*)d_in[3];
    const float* b1s   = (const float*)d_in[4];
    const float* W1d   = (const float*)d_in[5];
    const float* b1d   = (const float*)d_in[6];
    const float* attn1 = (const float*)d_in[7];
    const float* W2s   = (const float*)d_in[8];
    const float* b2s   = (const float*)d_in[9];
    const float* W2d   = (const float*)d_in[10];
    const float* b2d   = (const float*)d_in[11];
    const float* attn2 = (const float*)d_in[12];
    const float* Wn    = (const float*)d_in[13];
    const float* bn    = (const float*)d_in[14];
    float* out = (float*)d_out;

    __half* fs1h = (__half*)sym(g_fs1h);
    float* fd1  = (float*)sym(g_fd1);
    float* out1 = (float*)sym(g_out1);
    __half* fs2h = (__half*)sym(g_fs2h);
    float* fd2  = (float*)sym(g_fd2);
    float* out2 = (float*)sym(g_out2);
    int*   cnt  = (int*)sym(g_cnt);

    // side stream + events (host objects, created once; no device allocation)
    static cudaStream_t s2 = nullptr;
    static cudaEvent_t evFork = nullptr, evJoin = nullptr;
    if (!s2) {
        cudaStreamCreateWithFlags(&s2, cudaStreamNonBlocking);
        cudaEventCreateWithFlags(&evFork, cudaEventDisableTiming);
        cudaEventCreateWithFlags(&evJoin, cudaEventDisableTiming);
    }

    // fork: CSR build + output-bias init run concurrently with GEMM1
    cudaEventRecord(evFork, 0);
    cudaStreamWaitEvent(s2, evFork, 0);

    cudaMemsetAsync(cnt, 0, N_NODES * sizeof(int), s2);
    hist_k<<<N_EDGES / 1024, 1024, 0, s2>>>(dst);
    scan_k<<<1, 1024, 0, s2>>>();
    scatter_k<<<N_EDGES / 1024, 1024, 0, s2>>>(src, dst);
    initout_k<<<32, 1024, 0, s2>>>(out, bn);
    cudaEventRecord(evJoin, s2);

    // main stream: layer 1 projections (merged s/d): [16384,128] @ [128,512]
    tf32gemm_k<<<dim3(N_NODES / 128, HF / 128, 2), 256>>>(
        feat, 128, W1s, W1d, b1s, b1d, fs1h, fd1, HF, HF, 128);

    // join before first CSR consumer
    cudaStreamWaitEvent(0, evJoin, 0);

    gat1_k<<<N_NODES, 128>>>(attn1);

    // layer 2 projections (merged s/d): [16384,512] @ [512,128]
    tf32gemm_k<<<dim3(N_NODES / 128, HID / 128, 2), 256>>>(
        out1, HF, W2s, W2d, b2s, b2d, fs2h, fd2, HID, HID, 512);

    gat2_k<<<N_NODES, 128>>>(attn2);

    // head: [256, 8192] @ [8192, 128], split-K 16 (out pre-filled with bias)
    sgemm_atomic_k<<<dim3(256 / 64, 128 / 64, 16), 256>>>(out2, 8192, Wn, 128, out, 128, 512);
}

// round 17
// speedup vs baseline: 1.0235x; 1.0235x over previous
#include <cuda_runtime.h>
#include <math.h>

#define N_NODES 16384
#define N_EDGES 262144
#define HEADS   4
#define HID     128
#define HF      (HEADS * HID)   // 512
#define SLOPE   0.2f

// ---------------- scratch (device globals) ----------------------------------
__device__ float g_fs1[N_NODES * HF];
__device__ float g_fd1[N_NODES * HF];
__device__ float g_out1[N_NODES * HF];
__device__ float g_fs2[N_NODES * HID];
__device__ float g_fd2[N_NODES * HID];
__device__ float g_out2[N_NODES * HID];
__device__ int   g_cnt[N_NODES];
__device__ int   g_rowptr[N_NODES + 1];
__device__ int   g_cur[N_NODES];
__device__ int   g_csrc[N_EDGES];

// ---------------- CSR build --------------------------------------------------
__global__ void hist_k(const int* __restrict__ dst) {
    int i = blockIdx.x * blockDim.x + threadIdx.x;
    if (i < N_EDGES) atomicAdd(&g_cnt[dst[i]], 1);
}

__global__ void scan_k() {
    __shared__ int sh[1024];
    int t = threadIdx.x;
    int base = t * 16;
    int loc[16];
    int s = 0;
#pragma unroll
    for (int i = 0; i < 16; i++) { loc[i] = s; s += g_cnt[base + i]; }
    sh[t] = s;
    __syncthreads();
    for (int off = 1; off < 1024; off <<= 1) {
        int v = 0;
        if (t >= off) v = sh[t - off];
        __syncthreads();
        sh[t] += v;
        __syncthreads();
    }
    int pre = (t == 0) ? 0 : sh[t - 1];
#pragma unroll
    for (int i = 0; i < 16; i++) {
        int rp = pre + loc[i];
        g_rowptr[base + i] = rp;
        g_cur[base + i]    = rp;
    }
    if (t == 1023) g_rowptr[N_NODES] = sh[1023];
}

// scatter + output-bias prefill (folded initout; bounded extra writes)
__global__ void scatter_k(const int* __restrict__ src, const int* __restrict__ dst,
                          float* __restrict__ out, const float* __restrict__ bn) {
    int i = blockIdx.x * blockDim.x + threadIdx.x;
    if (i < 256 * 128) out[i] = bn[i & 127];
    if (i < N_EDGES) {
        int p = atomicAdd(&g_cur[dst[i]], 1);
        g_csrc[p] = src[i];
    }
}

// ---------------- helpers ----------------------------------------------------
__device__ __forceinline__ unsigned f2tf(float f) {
    unsigned u;
    asm("cvt.rna.tf32.f32 %0, %1;" : "=r"(u) : "f"(f));
    return u;
}

__device__ __forceinline__ void cpa16(void* s, const void* g) {
    unsigned sa = (unsigned)__cvta_generic_to_shared(s);
    asm volatile("cp.async.cg.shared.global [%0], [%1], 16;" :: "r"(sa), "l"(g));
}
#define CP_COMMIT() asm volatile("cp.async.commit_group;")
#define CP_WAIT(n)  asm volatile("cp.async.wait_group %0;" :: "n"(n))

// ---------------- tf32 GEMM (round-3 config, measured best) ------------------
__global__ __launch_bounds__(256)
void tf32gemm_k(const float* __restrict__ A, int lda,
                const float* __restrict__ B0, const float* __restrict__ B1,
                const float* __restrict__ bias0, const float* __restrict__ bias1,
                float* __restrict__ C0, float* __restrict__ C1,
                int ldb, int ldc, int K) {
    const float* B    = blockIdx.z ? B1 : B0;
    const float* bias = blockIdx.z ? bias1 : bias0;
    float*       C    = blockIdx.z ? C1 : C0;

    __shared__ float As[2][128][20];
    __shared__ float Bs[2][16][136];

    const int t = threadIdx.x;
    const int lane = t & 31, wid = t >> 5;
    const int warp_m = wid >> 2, warp_n = wid & 3;
    const int bm = blockIdx.x * 128, bn = blockIdx.y * 128;

    const int arow = t >> 1;
    const int ac   = (t & 1) * 8;
    const int brow = t >> 5;
    const int bc   = lane * 4;

    const float* Ag  = A + (size_t)(bm + arow) * lda + ac;
    const float* Bg0 = B + (size_t)brow * ldb + bn + bc;
    const float* Bg1 = B + (size_t)(brow + 8) * ldb + bn + bc;

    const int r_lo = lane >> 2;
    const int k_lo = lane & 3;
    const int nch = K >> 4;

    float acc[4][4][4];
#pragma unroll
    for (int i = 0; i < 4; i++)
#pragma unroll
        for (int j = 0; j < 4; j++)
#pragma unroll
            for (int k = 0; k < 4; k++) acc[i][j][k] = 0.f;

    auto issue = [&](int buf, int kc) {
        const float* ag = Ag + kc * 16;
        cpa16(&As[buf][arow][ac],     ag);
        cpa16(&As[buf][arow][ac + 4], ag + 4);
        cpa16(&Bs[buf][brow][bc],     Bg0 + (size_t)kc * 16 * ldb);
        cpa16(&Bs[buf][brow + 8][bc], Bg1 + (size_t)kc * 16 * ldb);
    };

    issue(0, 0);
    CP_COMMIT();

    for (int kc = 0; kc < nch; kc++) {
        if (kc + 1 < nch) {
            issue((kc + 1) & 1, kc + 1);
            CP_COMMIT();
            CP_WAIT(1);
        } else {
            CP_WAIT(0);
        }
        __syncthreads();

        const int buf = kc & 1;
#pragma unroll
        for (int ks = 0; ks < 16; ks += 8) {
            unsigned af[4][4], bf[4][2];
#pragma unroll
            for (int mf = 0; mf < 4; mf++) {
                int r0 = warp_m * 64 + mf * 16 + r_lo;
                int k0 = ks + k_lo;
                af[mf][0] = f2tf(As[buf][r0][k0]);
                af[mf][1] = f2tf(As[buf][r0 + 8][k0]);
                af[mf][2] = f2tf(As[buf][r0][k0 + 4]);
                af[mf][3] = f2tf(As[buf][r0 + 8][k0 + 4]);
            }
#pragma unroll
            for (int nf = 0; nf < 4; nf++) {
                int n0 = warp_n * 32 + nf * 8 + r_lo;
                int k0 = ks + k_lo;
                bf[nf][0] = f2tf(Bs[buf][k0][n0]);
                bf[nf][1] = f2tf(Bs[buf][k0 + 4][n0]);
            }
#pragma unroll
            for (int mf = 0; mf < 4; mf++)
#pragma unroll
                for (int nf = 0; nf < 4; nf++) {
                    asm("mma.sync.aligned.m16n8k8.row.col.f32.tf32.tf32.f32 "
                        "{%0,%1,%2,%3}, {%4,%5,%6,%7}, {%8,%9}, {%0,%1,%2,%3};"
                        : "+f"(acc[mf][nf][0]), "+f"(acc[mf][nf][1]),
                          "+f"(acc[mf][nf][2]), "+f"(acc[mf][nf][3])
                        : "r"(af[mf][0]), "r"(af[mf][1]), "r"(af[mf][2]), "r"(af[mf][3]),
                          "r"(bf[nf][0]), "r"(bf[nf][1]));
                }
        }
        __syncthreads();
    }

#pragma unroll
    for (int mf = 0; mf < 4; mf++) {
        int r = bm + warp_m * 64 + mf * 16 + r_lo;
#pragma unroll
        for (int nf = 0; nf < 4; nf++) {
            int c = bn + warp_n * 32 + nf * 8 + 2 * k_lo;
            float bb0 = bias[c], bb1 = bias[c + 1];
            float2 v0 = { acc[mf][nf][0] + bb0, acc[mf][nf][1] + bb1 };
            float2 v1 = { acc[mf][nf][2] + bb0, acc[mf][nf][3] + bb1 };
            *(float2*)&C[(size_t)r * ldc + c] = v0;
            *(float2*)&C[(size_t)(r + 8) * ldc + c] = v1;
        }
    }
}

// ---------------- fp32 SGEMM (head, split-K atomics) -------------------------
__global__ __launch_bounds__(256)
void sgemm_atomic_k(const float* __restrict__ A, int lda,
                    const float* __restrict__ B, int ldb,
                    float* __restrict__ C, int ldc,
                    int Kchunk) {
    __shared__ float As[16][68];
    __shared__ float Bs[16][64];
    int tid = threadIdx.x;
    int bm = blockIdx.x * 64, bn = blockIdx.y * 64;
    int kstart = blockIdx.z * Kchunk;
    int tx = tid & 15, ty = tid >> 4;

    int arow = tid >> 2;
    int akk  = (tid & 3) * 4;
    int brow = tid >> 4;
    int bcol = (tid & 15) * 4;

    const float* Ap = A + (size_t)(bm + arow) * lda + kstart + akk;
    const float* Bp = B + (size_t)(kstart + brow) * ldb + bn + bcol;

    float acc[4][4] = {};
    for (int k = 0; k < Kchunk; k += 16) {
        float4 a = *(const float4*)Ap; Ap += 16;
        float4 b = *(const float4*)Bp; Bp += (size_t)16 * ldb;
        As[akk + 0][arow] = a.x;
        As[akk + 1][arow] = a.y;
        As[akk + 2][arow] = a.z;
        As[akk + 3][arow] = a.w;
        *(float4*)&Bs[brow][bcol] = b;
        __syncthreads();
#pragma unroll
        for (int kk = 0; kk < 16; kk++) {
            float a0 = As[kk][ty * 4 + 0];
            float a1 = As[kk][ty * 4 + 1];
            float a2 = As[kk][ty * 4 + 2];
            float a3 = As[kk][ty * 4 + 3];
            float4 bq = *(const float4*)&Bs[kk][tx * 4];
            acc[0][0] += a0 * bq.x; acc[0][1] += a0 * bq.y; acc[0][2] += a0 * bq.z; acc[0][3] += a0 * bq.w;
            acc[1][0] += a1 * bq.x; acc[1][1] += a1 * bq.y; acc[1][2] += a1 * bq.z; acc[1][3] += a1 * bq.w;
            acc[2][0] += a2 * bq.x; acc[2][1] += a2 * bq.y; acc[2][2] += a2 * bq.z; acc[2][3] += a2 * bq.w;
            acc[3][0] += a3 * bq.x; acc[3][1] += a3 * bq.y; acc[3][2] += a3 * bq.z; acc[3][3] += a3 * bq.w;
        }
        __syncthreads();
    }
#pragma unroll
    for (int i = 0; i < 4; i++) {
        int row = bm + ty * 4 + i;
#pragma unroll
        for (int j = 0; j < 4; j++) {
            int col = bn + tx * 4 + j;
            atomicAdd(&C[(size_t)row * ldc + col], acc[i][j]);
        }
    }
}

// ---------------- GAT shared pieces ------------------------------------------
__device__ __forceinline__ float edge_dot(float4 fs, float4 fdv, float4 av) {
    float e0 = fs.x + fdv.x; e0 = e0 > 0.f ? e0 : SLOPE * e0;
    float e1 = fs.y + fdv.y; e1 = e1 > 0.f ? e1 : SLOPE * e1;
    float e2 = fs.z + fdv.z; e2 = e2 > 0.f ? e2 : SLOPE * e2;
    float e3 = fs.w + fdv.w; e3 = e3 > 0.f ? e3 : SLOPE * e3;
    return e0 * av.x + e1 * av.y + e2 * av.z + e3 * av.w;
}

__device__ __forceinline__ float wreduce(float d) {
#pragma unroll
    for (int o = 16; o; o >>= 1) d += __shfl_xor_sync(0xffffffffu, d, o);
    return d;
}

__device__ __forceinline__ void online_upd(float& m, float& ssum, float4& acc,
                                           float d, float4 fs) {
    float mn = fmaxf(m, d);
    float sc = __expf(m - mn);
    float p  = __expf(d - mn);
    ssum = ssum * sc + p;
    acc.x = acc.x * sc + p * fs.x;
    acc.y = acc.y * sc + p * fs.y;
    acc.z = acc.z * sc + p * fs.z;
    acc.w = acc.w * sc + p * fs.w;
    m = mn;
}

// ---------------- GAT layer 1: 4 warps (1 per head), 4x edge batching --------
__global__ __launch_bounds__(128)
void gat1_k(const float* __restrict__ attn1) {
    int n = blockIdx.x;
    int h = threadIdx.x >> 5;
    int lane = threadIdx.x & 31;
    __shared__ float s_fd[HF];
    __shared__ float s_at[HF];
    for (int i = threadIdx.x; i < HF; i += 128) {
        s_fd[i] = g_fd1[(size_t)n * HF + i];
        s_at[i] = attn1[i];
    }
    __syncthreads();

    int beg = g_rowptr[n], end = g_rowptr[n + 1];
    float4 fdv = *(const float4*)&s_fd[h * HID + lane * 4];
    float4 av  = *(const float4*)&s_at[h * HID + lane * 4];

    float m = -1e30f, ssum = 0.f;
    float4 acc = {0.f, 0.f, 0.f, 0.f};

    int e = beg;
    for (; e + 4 <= end; e += 4) {
        int s0 = g_csrc[e], s1 = g_csrc[e + 1], s2 = g_csrc[e + 2], s3 = g_csrc[e + 3];
        float4 f0 = *(const float4*)&g_fs1[(size_t)s0 * HF + h * HID + lane * 4];
        float4 f1 = *(const float4*)&g_fs1[(size_t)s1 * HF + h * HID + lane * 4];
        float4 f2 = *(const float4*)&g_fs1[(size_t)s2 * HF + h * HID + lane * 4];
        float4 f3 = *(const float4*)&g_fs1[(size_t)s3 * HF + h * HID + lane * 4];
        float d0 = wreduce(edge_dot(f0, fdv, av));
        float d1 = wreduce(edge_dot(f1, fdv, av));
        float d2 = wreduce(edge_dot(f2, fdv, av));
        float d3 = wreduce(edge_dot(f3, fdv, av));
        online_upd(m, ssum, acc, d0, f0);
        online_upd(m, ssum, acc, d1, f1);
        online_upd(m, ssum, acc, d2, f2);
        online_upd(m, ssum, acc, d3, f3);
    }
    for (; e < end; ++e) {
        int s = g_csrc[e];
        float4 fs = *(const float4*)&g_fs1[(size_t)s * HF + h * HID + lane * 4];
        float d = wreduce(edge_dot(fs, fdv, av));
        online_upd(m, ssum, acc, d, fs);
    }

    float inv = (end > beg) ? 1.f / ssum : 0.f;
    float4 v;
    v.x = acc.x * inv; v.x = v.x > 0.f ? v.x : expm1f(v.x);
    v.y = acc.y * inv; v.y = v.y > 0.f ? v.y : expm1f(v.y);
    v.z = acc.z * inv; v.z = v.z > 0.f ? v.z : expm1f(v.z);
    v.w = acc.w * inv; v.w = v.w > 0.f ? v.w : expm1f(v.w);
    *(float4*)&g_out1[(size_t)n * HF + h * HID + lane * 4] = v;
}

// ---------------- GAT layer 2: 4 warps, 2x batching --------------------------
__global__ __launch_bounds__(128)
void gat2_k(const float* __restrict__ attn2) {
    int n = blockIdx.x;
    int t = threadIdx.x;
    int warp = t >> 5, lane = t & 31;
    __shared__ float s_fd[HID];
    __shared__ float s_at[HID];
    __shared__ float s_m[4], s_s[4];
    __shared__ float s_acc[4][HID];
    if (t < HID) { s_fd[t] = g_fd2[(size_t)n * HID + t]; s_at[t] = attn2[t]; }
    __syncthreads();

    float4 fdv = *(const float4*)&s_fd[lane * 4];
    float4 av  = *(const float4*)&s_at[lane * 4];
    int beg = g_rowptr[n], end = g_rowptr[n + 1];

    float m = -1e30f, ssum = 0.f;
    float4 acc = {0.f, 0.f, 0.f, 0.f};
    int e = beg + warp;
    for (; e + 4 < end; e += 8) {
        int s0 = g_csrc[e], s1 = g_csrc[e + 4];
        float4 f0 = *(const float4*)&g_fs2[(size_t)s0 * HID + lane * 4];
        float4 f1 = *(const float4*)&g_fs2[(size_t)s1 * HID + lane * 4];
        float d0 = wreduce(edge_dot(f0, fdv, av));
        float d1 = wreduce(edge_dot(f1, fdv, av));
        online_upd(m, ssum, acc, d0, f0);
        online_upd(m, ssum, acc, d1, f1);
    }
    for (; e < end; e += 4) {
        int s = g_csrc[e];
        float4 fs = *(const float4*)&g_fs2[(size_t)s * HID + lane * 4];
        float d = wreduce(edge_dot(fs, fdv, av));
        online_upd(m, ssum, acc, d, fs);
    }
    if (lane == 0) { s_m[warp] = m; s_s[warp] = ssum; }
    *(float4*)&s_acc[warp][lane * 4] = acc;
    __syncthreads();

    if (t < HID) {
        float M = fmaxf(fmaxf(s_m[0], s_m[1]), fmaxf(s_m[2], s_m[3]));
        float S = s_s[0] * __expf(s_m[0] - M) + s_s[1] * __expf(s_m[1] - M) +
                  s_s[2] * __expf(s_m[2] - M) + s_s[3] * __expf(s_m[3] - M);
        float v = 0.f;
        if (S > 0.f) {
            v = s_acc[0][t] * __expf(s_m[0] - M) + s_acc[1][t] * __expf(s_m[1] - M) +
                s_acc[2][t] * __expf(s_m[2] - M) + s_acc[3][t] * __expf(s_m[3] - M);
            v /= S;
        }
        v = v > 0.f ? v : expm1f(v);
        g_out2[(size_t)n * HID + t] = v;
    }
}

// ---------------- launch -----------------------------------------------------
static void* sym(const void* s) { void* p = nullptr; cudaGetSymbolAddress(&p, s); return p; }

extern "C" void kernel_launch(void* const* d_in, const int* in_sizes, int n_in,
                              void* d_out, int out_size) {
    const float* feat  = (const float*)d_in[0];
    const int*   src   = (const int*)d_in[1];
    const int*   dst   = (const int*)d_in[2];
    const float* W1s   = (const float*)d_in[3];
    const float* b1s   = (const float*)d_in[4];
    const float* W1d   = (const float*)d_in[5];
    const float* b1d   = (const float*)d_in[6];
    const float* attn1 = (const float*)d_in[7];
    const float* W2s   = (const float*)d_in[8];
    const float* b2s   = (const float*)d_in[9];
    const float* W2d   = (const float*)d_in[10];
    const float* b2d   = (const float*)d_in[11];
    const float* attn2 = (const float*)d_in[12];
    const float* Wn    = (const float*)d_in[13];
    const float* bn    = (const float*)d_in[14];
    float* out = (float*)d_out;

    float* fs1  = (float*)sym(g_fs1);
    float* fd1  = (float*)sym(g_fd1);
    float* out1 = (float*)sym(g_out1);
    float* fs2  = (float*)sym(g_fs2);
    float* fd2  = (float*)sym(g_fd2);
    float* out2 = (float*)sym(g_out2);
    int*   cnt  = (int*)sym(g_cnt);

    // side stream + events (host objects, created once; no device allocation)
    static cudaStream_t s2 = nullptr;
    static cudaEvent_t evFork = nullptr, evJoin = nullptr;
    if (!s2) {
        cudaStreamCreateWithFlags(&s2, cudaStreamNonBlocking);
        cudaEventCreateWithFlags(&evFork, cudaEventDisableTiming);
        cudaEventCreateWithFlags(&evJoin, cudaEventDisableTiming);
    }

    // fork: CSR build + output-bias prefill run concurrently with GEMM1
    cudaEventRecord(evFork, 0);
    cudaStreamWaitEvent(s2, evFork, 0);

    cudaMemsetAsync(cnt, 0, N_NODES * sizeof(int), s2);
    hist_k<<<N_EDGES / 1024, 1024, 0, s2>>>(dst);
    scan_k<<<1, 1024, 0, s2>>>();
    scatter_k<<<N_EDGES / 1024, 1024, 0, s2>>>(src, dst, out, bn);
    cudaEventRecord(evJoin, s2);

    // main stream: layer 1 projections (merged s/d): [16384,128] @ [128,512]
    tf32gemm_k<<<dim3(N_NODES / 128, HF / 128, 2), 256>>>(
        feat, 128, W1s, W1d, b1s, b1d, fs1, fd1, HF, HF, 128);

    // join before first CSR consumer
    cudaStreamWaitEvent(0, evJoin, 0);

    gat1_k<<<N_NODES, 128>>>(attn1);

    // layer 2 projections (merged s/d): [16384,512] @ [512,128]
    tf32gemm_k<<<dim3(N_NODES / 128, HID / 128, 2), 256>>>(
        out1, HF, W2s, W2d, b2s, b2d, fs2, fd2, HID, HID, 512);

    gat2_k<<<N_NODES, 128>>>(attn2);

    // head: [256, 8192] @ [8192, 128], split-K 16 (out pre-filled with bias)
    sgemm_atomic_k<<<dim3(256 / 64, 128 / 64, 16), 256>>>(out2, 8192, Wn, 128, out, 128, 512);
}